// round 14
// baseline (speedup 1.0000x reference)
#include <cuda_runtime.h>
#include <math.h>

#define BATCH 2
#define NPT   1000
#define KNN   8
#define NPAIR 499500   // N*(N-1)/2

typedef unsigned long long u64;

// ---------------- static scratch (no allocation allowed) ----------------
__device__ float g_x1[BATCH * NPT * 32];
__device__ float g_x2[BATCH * NPT * 128];
__device__ float g_x3[BATCH * NPT * 512];
__device__ int   g_idx[BATCH * NPT * KNN];
__device__ float g_A [BATCH * NPT * 256];
__device__ float g_Bv[BATCH * NPT * 256];
__device__ float g_sf[BATCH * NPT * 128];
__device__ float g_hi[BATCH * NPT * 128];
__device__ float g_hj[BATCH * NPT * 128];
__device__ float g_hg[BATCH * 128];
__device__ float g_d2[(size_t)BATCH * NPT * NPT];
__device__ u64 g_w2p  [128 * 512];   // conv3 w2 packed f32x2 over h, [h2][col]
__device__ u64 g_smw1p[336 * 256];   // sm_w1 packed over d
__device__ u64 g_smw2p[128 * 128];   // sm_w2 packed over d
__device__ u64 g_ecw1p[128 * 128];   // ec_w1[:256] packed over d (two 64x128 halves)

// ---------------- f32x2 packed helpers ----------------
__device__ __forceinline__ u64 ffma2(u64 a, u64 b, u64 c) {
    u64 d;
    asm("fma.rn.f32x2 %0, %1, %2, %3;" : "=l"(d) : "l"(a), "l"(b), "l"(c));
    return d;
}
__device__ __forceinline__ void unpack2(u64 v, float& lo, float& hi) {
    asm("mov.b64 {%0, %1}, %2;" : "=f"(lo), "=f"(hi) : "l"(v));
}
__device__ __forceinline__ u64 pack2(float lo, float hi) {
    u64 v;
    asm("mov.b64 %0, {%1, %2};" : "=l"(v) : "f"(lo), "f"(hi));
    return v;
}

// ---------------- combined weight packing ----------------
#define PK_W2   (128 * 512)
#define PK_SMW1 (336 * 256)
#define PK_SMW2 (128 * 128)
#define PK_EC   (128 * 128)
#define PK_TOTAL (PK_W2 + PK_SMW1 + PK_SMW2 + PK_EC)
__global__ void pack_all_kernel(const float* __restrict__ c3w2, const float* __restrict__ smw1,
                                const float* __restrict__ smw2, const float* __restrict__ ecw1,
                                u64* __restrict__ w2p, u64* __restrict__ smw1p,
                                u64* __restrict__ smw2p, u64* __restrict__ ecw1p) {
    int idx = blockIdx.x * blockDim.x + threadIdx.x;
    if (idx < PK_W2) {
        int h2 = idx >> 9, col = idx & 511;
        w2p[idx] = pack2(c3w2[(2 * h2) * 512 + col], c3w2[(2 * h2 + 1) * 512 + col]);
        return;
    }
    idx -= PK_W2;
    if (idx < PK_SMW1) {
        int d2 = idx >> 8, col = idx & 255;
        smw1p[idx] = pack2(smw1[(2 * d2) * 256 + col], smw1[(2 * d2 + 1) * 256 + col]);
        return;
    }
    idx -= PK_SMW1;
    if (idx < PK_SMW2) {
        int d2 = idx >> 7, col = idx & 127;
        smw2p[idx] = pack2(smw2[(2 * d2) * 128 + col], smw2[(2 * d2 + 1) * 128 + col]);
        return;
    }
    idx -= PK_SMW2;
    {
        int half = idx >= 64 * 128;
        int i = idx - half * 64 * 128;
        int d2 = i >> 7, col = i & 127;
        int r0 = half * 128 + 2 * d2;
        ecw1p[idx] = pack2(ecw1[r0 * 128 + col], ecw1[(r0 + 1) * 128 + col]);
    }
}

// ---------------- pairwise ranking value: s[i][j] = |xj|^2 - 2*dot(xi,xj) ----------------
__global__ void d2_kernel(const float* __restrict__ x, int C, float* __restrict__ out) {
    int b  = blockIdx.z;
    int i0 = blockIdx.y * 64;
    int j0 = blockIdx.x * 64;
    __shared__ float xaT[16][72];
    __shared__ float xbT[16][72];

    int tid = threadIdx.x;          // 256
    int tx = tid & 15, ty = tid >> 4;

    float dot[4][4];
    float sqj[4];
#pragma unroll
    for (int v = 0; v < 4; v++) sqj[v] = 0.f;
#pragma unroll
    for (int u = 0; u < 4; u++)
#pragma unroll
        for (int v = 0; v < 4; v++) dot[u][v] = 0.f;

    for (int k0 = 0; k0 < C; k0 += 16) {
        for (int t = tid; t < 2048; t += 256) {
            int half = t >> 10;
            int r  = (t >> 4) & 63;
            int kk = t & 15;
            int cc = k0 + kk;
            int nn = (half ? j0 : i0) + r;
            float v = 0.f;
            if (cc < C && nn < NPT) v = x[((size_t)(b * NPT + nn)) * C + cc];
            if (half) xbT[kk][r] = v; else xaT[kk][r] = v;
        }
        __syncthreads();
#pragma unroll
        for (int kk = 0; kk < 16; kk++) {
            float4 a  = *reinterpret_cast<const float4*>(&xaT[kk][ty * 4]);
            float4 bb = *reinterpret_cast<const float4*>(&xbT[kk][tx * 4]);
            float av[4] = {a.x, a.y, a.z, a.w};
            float bv[4] = {bb.x, bb.y, bb.z, bb.w};
#pragma unroll
            for (int v = 0; v < 4; v++) sqj[v] = fmaf(bv[v], bv[v], sqj[v]);
#pragma unroll
            for (int u = 0; u < 4; u++)
#pragma unroll
                for (int v = 0; v < 4; v++)
                    dot[u][v] = fmaf(av[u], bv[v], dot[u][v]);
        }
        __syncthreads();
    }
#pragma unroll
    for (int u = 0; u < 4; u++) {
        int i = i0 + ty * 4 + u;
        if (i >= NPT) continue;
#pragma unroll
        for (int v = 0; v < 4; v++) {
            int j = j0 + tx * 4 + v;
            if (j >= NPT) continue;
            out[(size_t)(b * NPT + i) * NPT + j] = sqj[v] - 2.f * dot[u][v];
        }
    }
}

// ---------------- top-8 per row: TWO warps per row, branchless insert ----------------
__global__ void topk_kernel(const float* __restrict__ d2, int* __restrict__ idxout) {
    int warp = threadIdx.x >> 5, lane = threadIdx.x & 31;
    int r = warp >> 1;
    int h = warp & 1;
    int node = blockIdx.x * 4 + r;
    const float* row = d2 + (size_t)node * NPT;
    int L = h * 32 + lane;

    float bd[8]; int bi[8];
#pragma unroll
    for (int s = 0; s < 8; s++) { bd[s] = 3.4e38f; bi[s] = 0x7fffffff; }

#pragma unroll
    for (int cc = 0; cc < 2; cc++) {
        float v[8]; int jj[8];
#pragma unroll
        for (int q = 0; q < 8; q++) {
            int j = ((cc * 8 + q) * 2 + h) * 32 + lane;
            jj[q] = j;
            v[q] = (j < NPT) ? row[j] : 3.4e38f;
        }
#pragma unroll
        for (int q = 0; q < 8; q++) {
            float vv = v[q]; int vj = jj[q];
#pragma unroll
            for (int s = 0; s < 8; s++) {
                bool take = vv < bd[s];
                float tb = bd[s]; int ti = bi[s];
                bd[s] = take ? vv : tb;
                bi[s] = take ? vj : ti;
                vv = take ? tb : vv;
                vj = take ? ti : vj;
            }
        }
    }

    __shared__ float sd[4][64][8];
    __shared__ int   si[4][64][8];
#pragma unroll
    for (int s = 0; s < 8; s++) { sd[r][L][s] = bd[s]; si[r][L][s] = bi[s]; }
    __syncthreads();

    for (int str = 32; str > 0; str >>= 1) {
        if (L < str) {
            float* A1 = sd[r][L];        int* I1 = si[r][L];
            float* A2 = sd[r][L + str];  int* I2 = si[r][L + str];
            float od[8]; int oi[8];
            int a = 0, c2 = 0;
#pragma unroll
            for (int t = 0; t < 8; t++) {
                bool takeA = (A1[a] < A2[c2]) || (A1[a] == A2[c2] && I1[a] <= I2[c2]);
                if (takeA) { od[t] = A1[a]; oi[t] = I1[a]; a++; }
                else       { od[t] = A2[c2]; oi[t] = I2[c2]; c2++; }
            }
#pragma unroll
            for (int t = 0; t < 8; t++) { A1[t] = od[t]; I1[t] = oi[t]; }
        }
        __syncthreads();
    }
    if (L < 8) idxout[(size_t)node * 8 + L] = si[r][0][L];
}

// ---------------- small ab: one thread per (node, h) output ----------------
__global__ void ab_small_kernel(const float* __restrict__ x, const float* __restrict__ w1,
                                int C, int H, float* __restrict__ A, float* __restrict__ Bv) {
    int gid = blockIdx.x * blockDim.x + threadIdx.x;
    if (gid >= BATCH * NPT * H) return;
    int node = gid / H, h = gid % H;
    const float* xr = x + (size_t)node * C;
    float a = 0.f, bb = 0.f;
    for (int c = 0; c < C; c++) {
        float v = xr[c];
        a  = fmaf(v, w1[c * H + h],       a);
        bb = fmaf(v, w1[(C + c) * H + h], bb);
    }
    A[gid] = a; Bv[gid] = bb;
}

// ---------------- big ab (conv3): 8 nodes/block, 256 threads ----------------
template<int NPB>
__global__ void ab_kernel(const float* __restrict__ x, const float* __restrict__ w1,
                          int C, int H, float* __restrict__ A, float* __restrict__ Bv) {
    int n0 = blockIdx.x * NPB;
    int tid = threadIdx.x;          // H threads
    __shared__ float xs[NPB][128];
    for (int t = tid; t < NPB * C; t += blockDim.x) {
        int nn = t / C, c = t % C;
        xs[nn][c] = x[(size_t)(n0 + nn) * C + c];
    }
    __syncthreads();
    float a[NPB], bb[NPB];
#pragma unroll
    for (int nn = 0; nn < NPB; nn++) { a[nn] = 0.f; bb[nn] = 0.f; }
    for (int c = 0; c < C; c++) {
        float wt = w1[c * H + tid];
        float wb = w1[(C + c) * H + tid];
#pragma unroll
        for (int nn = 0; nn < NPB; nn++) {
            float v = xs[nn][c];
            a[nn]  = fmaf(v, wt, a[nn]);
            bb[nn] = fmaf(v, wb, bb[nn]);
        }
    }
#pragma unroll
    for (int nn = 0; nn < NPB; nn++) {
        A [(size_t)(n0 + nn) * H + tid] = a[nn];
        Bv[(size_t)(n0 + nn) * H + tid] = bb[nn];
    }
}

// ---------------- conv1 edge: warp-per-node, 256 threads = 8 nodes/block ----------------
__global__ void edge1_kernel(const float* __restrict__ A, const float* __restrict__ Bv,
                             const int* __restrict__ idx, const float* __restrict__ b1,
                             const float* __restrict__ w2, const float* __restrict__ b2,
                             float* __restrict__ xout) {
    const int H = 16, COUT = 32;
    int warp = threadIdx.x >> 5, lane = threadIdx.x & 31;
    int node = blockIdx.x * 8 + warp;
    int bbase = (node / NPT) * NPT;

    __shared__ float aic[8][H];
    __shared__ float hsh[8][KNN][H];
    __shared__ int   js[8][KNN];

    if (lane < KNN) js[warp][lane] = idx[(size_t)node * KNN + lane];
    if (lane < H)
        aic[warp][lane] = A[(size_t)node * H + lane] - Bv[(size_t)node * H + lane] + b1[lane];
    __syncwarp();

#pragma unroll
    for (int q = 0; q < 4; q++) {
        int t = lane + q * 32;
        int k = t >> 4, hh = t & 15;
        hsh[warp][k][hh] = fmaxf(aic[warp][hh] + Bv[(size_t)(bbase + js[warp][k]) * H + hh], 0.f);
    }
    __syncwarp();

    float acc[KNN];
#pragma unroll
    for (int k = 0; k < KNN; k++) acc[k] = 0.f;
#pragma unroll
    for (int hh = 0; hh < H; hh++) {
        float w = w2[hh * COUT + lane];
#pragma unroll
        for (int k = 0; k < KNN; k++) acc[k] = fmaf(hsh[warp][k][hh], w, acc[k]);
    }
    float m = acc[0];
#pragma unroll
    for (int k = 1; k < KNN; k++) m = fmaxf(m, acc[k]);
    xout[(size_t)node * COUT + lane] = m + b2[lane];
}

// ---------------- edge MLP2 + max, generic (conv2) ----------------
template<int H, int COUT, int T, int VC, int NPB>
__global__ void edge_kernel(const float* __restrict__ A, const float* __restrict__ Bv,
                            const int* __restrict__ idx, const float* __restrict__ b1,
                            const float* __restrict__ w2, const float* __restrict__ b2,
                            float* __restrict__ xout) {
    static_assert(T * VC == COUT, "layout");
    int n0 = blockIdx.x * NPB;
    int tid = threadIdx.x;
    __shared__ float aic[NPB][H];
    __shared__ float hsh[NPB][KNN][H];
    __shared__ int   js[NPB][KNN];

    for (int t = tid; t < NPB * KNN; t += T)
        js[t / KNN][t % KNN] = idx[(size_t)(n0 + t / KNN) * KNN + t % KNN];
#pragma unroll
    for (int n = 0; n < NPB; n++)
        for (int hh = tid; hh < H; hh += T)
            aic[n][hh] = A[(size_t)(n0 + n) * H + hh] - Bv[(size_t)(n0 + n) * H + hh] + b1[hh];
    __syncthreads();

    int bbase = (n0 / NPT) * NPT;
#pragma unroll
    for (int n = 0; n < NPB; n++)
#pragma unroll
        for (int k = 0; k < KNN; k++) {
            const float* bvj = Bv + (size_t)(bbase + js[n][k]) * H;
            for (int hh = tid; hh < H; hh += T)
                hsh[n][k][hh] = fmaxf(aic[n][hh] + bvj[hh], 0.f);
        }
    __syncthreads();

    float acc[NPB][KNN][VC];
#pragma unroll
    for (int n = 0; n < NPB; n++)
#pragma unroll
        for (int k = 0; k < KNN; k++)
#pragma unroll
            for (int v = 0; v < VC; v++) acc[n][k][v] = 0.f;

#pragma unroll 2
    for (int hh = 0; hh < H; hh++) {
        float w[VC];
#pragma unroll
        for (int v = 0; v < VC; v++) w[v] = w2[(size_t)hh * COUT + tid * VC + v];
#pragma unroll
        for (int n = 0; n < NPB; n++)
#pragma unroll
            for (int k = 0; k < KNN; k++) {
                float hv = hsh[n][k][hh];
#pragma unroll
                for (int v = 0; v < VC; v++) acc[n][k][v] = fmaf(hv, w[v], acc[n][k][v]);
            }
    }

#pragma unroll
    for (int n = 0; n < NPB; n++)
#pragma unroll
        for (int v = 0; v < VC; v++) {
            float m = -3.4e38f;
#pragma unroll
            for (int k = 0; k < KNN; k++) m = fmaxf(m, acc[n][k][v]);
            xout[(size_t)(n0 + n) * COUT + tid * VC + v] = m + b2[tid * VC + v];
        }
}

// ---------------- edge conv3: f32x2 packed, coalesced packed weights ----------------
#define E3_NPB 2
__global__ void edge3_kernel(const float* __restrict__ A, const float* __restrict__ Bv,
                             const int* __restrict__ idx, const float* __restrict__ b1,
                             const u64* __restrict__ w2p,
                             const float* __restrict__ b2,
                             float* __restrict__ xout) {
    const int H = 256, COUT = 512;
    int n0 = blockIdx.x * E3_NPB;
    int tid = threadIdx.x;   // 256
    __shared__ __align__(16) float hsh[E3_NPB][KNN][H];
    __shared__ __align__(16) float aic[E3_NPB][H];
    __shared__ int js[E3_NPB][KNN];

    for (int t = tid; t < E3_NPB * KNN; t += 256)
        js[t / KNN][t % KNN] = idx[(size_t)(n0 + t / KNN) * KNN + t % KNN];
#pragma unroll
    for (int n = 0; n < E3_NPB; n++)
        for (int hh = tid; hh < H; hh += 256)
            aic[n][hh] = A[(size_t)(n0 + n) * H + hh] - Bv[(size_t)(n0 + n) * H + hh] + b1[hh];
    __syncthreads();

    int bbase = (n0 / NPT) * NPT;
#pragma unroll
    for (int n = 0; n < E3_NPB; n++)
#pragma unroll
        for (int k = 0; k < KNN; k++) {
            const float* bvj = Bv + (size_t)(bbase + js[n][k]) * H;
            for (int hh = tid; hh < H; hh += 256)
                hsh[n][k][hh] = fmaxf(aic[n][hh] + bvj[hh], 0.f);
        }
    __syncthreads();

    u64 acc[E3_NPB][KNN][2];
#pragma unroll
    for (int n = 0; n < E3_NPB; n++)
#pragma unroll
        for (int k = 0; k < KNN; k++) { acc[n][k][0] = 0ull; acc[n][k][1] = 0ull; }

#pragma unroll 2
    for (int h2 = 0; h2 < H / 2; h2++) {
        u64 w0 = w2p[h2 * COUT + tid];
        u64 w1 = w2p[h2 * COUT + 256 + tid];
#pragma unroll
        for (int n = 0; n < E3_NPB; n++)
#pragma unroll
            for (int k = 0; k < KNN; k++) {
                u64 hv = reinterpret_cast<const u64*>(hsh[n][k])[h2];
                acc[n][k][0] = ffma2(hv, w0, acc[n][k][0]);
                acc[n][k][1] = ffma2(hv, w1, acc[n][k][1]);
            }
    }

#pragma unroll
    for (int n = 0; n < E3_NPB; n++) {
#pragma unroll
        for (int v = 0; v < 2; v++) {
            float m = -3.4e38f;
#pragma unroll
            for (int k = 0; k < KNN; k++) {
                float lo, hi;
                unpack2(acc[n][k][v], lo, hi);
                m = fmaxf(m, lo + hi);
            }
            int col = tid + v * 256;
            xout[(size_t)(n0 + n) * COUT + col] = m + b2[col];
        }
    }
}

// ---------------- sf = MLP(concat(x1,x2,x3)) + hi/hj projections, f32x2 ----------------
#define SF_NPB 8
__global__ void sf_kernel(const float* __restrict__ x1, const float* __restrict__ x2,
                          const float* __restrict__ x3,
                          const u64* __restrict__ w1p, const float* __restrict__ b1,
                          const u64* __restrict__ w2p, const float* __restrict__ b2,
                          const u64* __restrict__ ecw1p,
                          float* __restrict__ sf, float* __restrict__ hi, float* __restrict__ hj) {
    int n0 = blockIdx.x * SF_NPB;
    int tid = threadIdx.x;   // 256
    __shared__ __align__(16) float xin[SF_NPB][672];
    __shared__ __align__(16) float hsh[SF_NPB][256];
    __shared__ __align__(16) float sfs[SF_NPB][128];

    for (int t = tid; t < SF_NPB * 32; t += 256)
        xin[t >> 5][t & 31] = x1[(size_t)(n0 + (t >> 5)) * 32 + (t & 31)];
    for (int t = tid; t < SF_NPB * 128; t += 256)
        xin[t >> 7][32 + (t & 127)] = x2[(size_t)(n0 + (t >> 7)) * 128 + (t & 127)];
    for (int t = tid; t < SF_NPB * 512; t += 256)
        xin[t >> 9][160 + (t & 511)] = x3[(size_t)(n0 + (t >> 9)) * 512 + (t & 511)];
    __syncthreads();

    {
        u64 acc2[SF_NPB];
#pragma unroll
        for (int n = 0; n < SF_NPB; n++) acc2[n] = 0ull;
#pragma unroll 2
        for (int d2 = 0; d2 < 336; d2++) {
            u64 wv = w1p[d2 * 256 + tid];
#pragma unroll
            for (int n = 0; n < SF_NPB; n++) {
                u64 xv = reinterpret_cast<const u64*>(xin[n])[d2];
                acc2[n] = ffma2(xv, wv, acc2[n]);
            }
        }
        float bv = b1[tid];
#pragma unroll
        for (int n = 0; n < SF_NPB; n++) {
            float lo, hi2;
            unpack2(acc2[n], lo, hi2);
            hsh[n][tid] = fmaxf(lo + hi2 + bv, 0.f);
        }
    }
    __syncthreads();

    int col = tid & 127;
    int gn = (tid >> 7) * (SF_NPB / 2);
    {
        u64 acc2[SF_NPB / 2];
#pragma unroll
        for (int n = 0; n < SF_NPB / 2; n++) acc2[n] = 0ull;
#pragma unroll 4
        for (int d2 = 0; d2 < 128; d2++) {
            u64 wv = w2p[d2 * 128 + col];
#pragma unroll
            for (int n = 0; n < SF_NPB / 2; n++) {
                u64 hv = reinterpret_cast<const u64*>(hsh[gn + n])[d2];
                acc2[n] = ffma2(hv, wv, acc2[n]);
            }
        }
        float bv = b2[col];
#pragma unroll
        for (int n = 0; n < SF_NPB / 2; n++) {
            float lo, hi2;
            unpack2(acc2[n], lo, hi2);
            float v = lo + hi2 + bv;
            sfs[gn + n][col] = v;
            sf[(size_t)(n0 + gn + n) * 128 + col] = v;
        }
    }
    __syncthreads();

    {
        u64 a1[SF_NPB / 2], a2[SF_NPB / 2];
#pragma unroll
        for (int n = 0; n < SF_NPB / 2; n++) { a1[n] = 0ull; a2[n] = 0ull; }
#pragma unroll 4
        for (int d2 = 0; d2 < 64; d2++) {
            u64 wt = ecw1p[d2 * 128 + col];
            u64 wb = ecw1p[(64 + d2) * 128 + col];
#pragma unroll
            for (int n = 0; n < SF_NPB / 2; n++) {
                u64 s = reinterpret_cast<const u64*>(sfs[gn + n])[d2];
                a1[n] = ffma2(s, wt, a1[n]);
                a2[n] = ffma2(s, wb, a2[n]);
            }
        }
#pragma unroll
        for (int n = 0; n < SF_NPB / 2; n++) {
            float lo, hi2;
            unpack2(a1[n], lo, hi2);
            hi[(size_t)(n0 + gn + n) * 128 + col] = lo + hi2;
            unpack2(a2[n], lo, hi2);
            hj[(size_t)(n0 + gn + n) * 128 + col] = lo + hi2;
        }
    }
}

// ---------------- global max pool + hg, parallel ----------------
__global__ void gmax_kernel(const float* __restrict__ sf, const float* __restrict__ ecw1,
                            const float* __restrict__ ecb1, float* __restrict__ hg) {
    int b = blockIdx.x;
    int tid = threadIdx.x;  // 1024
    int col = tid & 127, seg = tid >> 7;
    __shared__ float part[8][128];
    __shared__ float gsh[128];
    float m = -3.4e38f;
    for (int n = seg; n < NPT; n += 8)
        m = fmaxf(m, sf[(size_t)(b * NPT + n) * 128 + col]);
    part[seg][col] = m;
    __syncthreads();
    if (tid < 128) {
        float mm = part[0][tid];
#pragma unroll
        for (int s = 1; s < 8; s++) mm = fmaxf(mm, part[s][tid]);
        gsh[tid] = mm;
    }
    __syncthreads();
    if (tid < 128) {
        float acc = ecb1[tid];
#pragma unroll 8
        for (int d = 0; d < 128; d++)
            acc = fmaf(gsh[d], ecw1[(256 + d) * 128 + tid], acc);
        hg[b * 128 + tid] = acc;
    }
}

// ---------------- all-pairs: 64x64 pair tiles, 4x4 register block ----------------
__global__ void pairs_kernel(const float* __restrict__ hi, const float* __restrict__ hj,
                             const float* __restrict__ hg, const float* __restrict__ ecw2,
                             const float* __restrict__ ecb2, float* __restrict__ out,
                             int writeBoth) {
    int it = blockIdx.x, jt = blockIdx.y, b = blockIdx.z;
    if (jt < it) return;

    __shared__ float his[16][68];
    __shared__ float hjs[16][68];
    __shared__ float w2s[128];

    int tid = threadIdx.x;  // 256
    if (tid < 128) w2s[tid] = ecw2[tid];
    int tx = tid & 15, ty = tid >> 4;

    float acc[4][4];
#pragma unroll
    for (int u = 0; u < 4; u++)
#pragma unroll
        for (int v = 0; v < 4; v++) acc[u][v] = 0.f;

    for (int c0 = 0; c0 < 128; c0 += 16) {
        __syncthreads();
        for (int t = tid; t < 1024; t += 256) {
            int r = t >> 4, c = t & 15;
            int gi = it * 64 + r;
            his[c][r] = (gi < NPT)
                ? hi[(size_t)(b * NPT + gi) * 128 + c0 + c] + hg[b * 128 + c0 + c] : 0.f;
            int gj = jt * 64 + r;
            hjs[c][r] = (gj < NPT) ? hj[(size_t)(b * NPT + gj) * 128 + c0 + c] : 0.f;
        }
        __syncthreads();
#pragma unroll
        for (int c = 0; c < 16; c++) {
            float w = w2s[c0 + c];
            float4 a  = *reinterpret_cast<const float4*>(&his[c][ty * 4]);
            float4 bb = *reinterpret_cast<const float4*>(&hjs[c][tx * 4]);
            float av[4] = {a.x, a.y, a.z, a.w};
            float bv[4] = {bb.x, bb.y, bb.z, bb.w};
#pragma unroll
            for (int u = 0; u < 4; u++)
#pragma unroll
                for (int v = 0; v < 4; v++)
                    acc[u][v] = fmaf(fmaxf(av[u] + bv[v], 0.f), w, acc[u][v]);
        }
    }

    float bias = ecb2[0];
#pragma unroll
    for (int u = 0; u < 4; u++) {
        int i = it * 64 + ty * 4 + u;
        if (i >= NPT) continue;
        size_t rowbase = (size_t)b * NPAIR
                       + (size_t)i * (NPT - 1) - (size_t)i * (i - 1) / 2 - i - 1;
#pragma unroll
        for (int v = 0; v < 4; v++) {
            int j = jt * 64 + tx * 4 + v;
            if (j >= NPT || j <= i) continue;
            float val = acc[u][v] + bias;
            float prob = 1.f / (1.f + __expf(-val));
            size_t o = rowbase + j;
            out[o] = prob;
            if (writeBoth) out[(size_t)BATCH * NPAIR + o] = val;
        }
    }
}

// ---------------- stream/event context (created once, host-side only) ----------------
struct OverlapCtx {
    cudaStream_t s1;
    cudaEvent_t e0, eA1, eX1, eA2, eX2, eA3;
    OverlapCtx() {
        cudaStreamCreateWithFlags(&s1, cudaStreamNonBlocking);
        unsigned f = cudaEventDisableTiming;
        cudaEventCreateWithFlags(&e0, f);
        cudaEventCreateWithFlags(&eA1, f);
        cudaEventCreateWithFlags(&eX1, f);
        cudaEventCreateWithFlags(&eA2, f);
        cudaEventCreateWithFlags(&eX2, f);
        cudaEventCreateWithFlags(&eA3, f);
    }
};
static OverlapCtx& octx() { static OverlapCtx c; return c; }

// ---------------- host launch ----------------
extern "C" void kernel_launch(void* const* d_in, const int* in_sizes, int n_in,
                              void* d_out, int out_size) {
    const float* pos   = (const float*)d_in[0];
    const float* c1_w1 = (const float*)d_in[1];
    const float* c1_b1 = (const float*)d_in[2];
    const float* c1_w2 = (const float*)d_in[3];
    const float* c1_b2 = (const float*)d_in[4];
    const float* c2_w1 = (const float*)d_in[5];
    const float* c2_b1 = (const float*)d_in[6];
    const float* c2_w2 = (const float*)d_in[7];
    const float* c2_b2 = (const float*)d_in[8];
    const float* c3_w1 = (const float*)d_in[9];
    const float* c3_b1 = (const float*)d_in[10];
    const float* c3_w2 = (const float*)d_in[11];
    const float* c3_b2 = (const float*)d_in[12];
    const float* sm_w1 = (const float*)d_in[13];
    const float* sm_b1 = (const float*)d_in[14];
    const float* sm_w2 = (const float*)d_in[15];
    const float* sm_b2 = (const float*)d_in[16];
    const float* ec_w1 = (const float*)d_in[17];
    const float* ec_b1 = (const float*)d_in[18];
    const float* ec_w2 = (const float*)d_in[19];
    const float* ec_b2 = (const float*)d_in[20];

    float *gx1, *gx2, *gx3, *gA, *gB, *gsf, *ghi, *ghj, *ghg, *gd2;
    u64 *gw2p, *gsmw1p, *gsmw2p, *gecw1p;
    int* gidx;
    cudaGetSymbolAddress((void**)&gx1, g_x1);
    cudaGetSymbolAddress((void**)&gx2, g_x2);
    cudaGetSymbolAddress((void**)&gx3, g_x3);
    cudaGetSymbolAddress((void**)&gidx, g_idx);
    cudaGetSymbolAddress((void**)&gA,  g_A);
    cudaGetSymbolAddress((void**)&gB,  g_Bv);
    cudaGetSymbolAddress((void**)&gsf, g_sf);
    cudaGetSymbolAddress((void**)&ghi, g_hi);
    cudaGetSymbolAddress((void**)&ghj, g_hj);
    cudaGetSymbolAddress((void**)&ghg, g_hg);
    cudaGetSymbolAddress((void**)&gd2, g_d2);
    cudaGetSymbolAddress((void**)&gw2p, g_w2p);
    cudaGetSymbolAddress((void**)&gsmw1p, g_smw1p);
    cudaGetSymbolAddress((void**)&gsmw2p, g_smw2p);
    cudaGetSymbolAddress((void**)&gecw1p, g_ecw1p);

    const int NB = BATCH * NPT;
    OverlapCtx& c = octx();
    cudaStream_t s0 = 0;
    cudaStream_t s1 = c.s1;
    dim3 dg(16, 16, BATCH);

    cudaEventRecord(c.e0, s0);
    cudaStreamWaitEvent(s1, c.e0, 0);

    pack_all_kernel<<<(PK_TOTAL + 255) / 256, 256, 0, s1>>>(c3_w2, sm_w1, sm_w2, ec_w1,
                                                            gw2p, gsmw1p, gsmw2p, gecw1p);
    ab_small_kernel<<<(NB * 16 + 255) / 256, 256, 0, s1>>>(pos, c1_w1, 3, 16, gA, gB);
    cudaEventRecord(c.eA1, s1);

    d2_kernel<<<dg, 256, 0, s0>>>(pos, 3, gd2);
    topk_kernel<<<NB / 4, 256, 0, s0>>>(gd2, gidx);

    cudaStreamWaitEvent(s0, c.eA1, 0);
    edge1_kernel<<<NB / 8, 256, 0, s0>>>(gA, gB, gidx, c1_b1, c1_w2, c1_b2, gx1);
    cudaEventRecord(c.eX1, s0);

    cudaStreamWaitEvent(s1, c.eX1, 0);
    ab_small_kernel<<<(NB * 64 + 255) / 256, 256, 0, s1>>>(gx1, c2_w1, 32, 64, gA, gB);
    cudaEventRecord(c.eA2, s1);

    d2_kernel<<<dg, 256, 0, s0>>>(gx1, 32, gd2);
    topk_kernel<<<NB / 4, 256, 0, s0>>>(gd2, gidx);

    cudaStreamWaitEvent(s0, c.eA2, 0);
    edge_kernel<64, 128, 128, 1, 4><<<NB / 4, 128, 0, s0>>>(gA, gB, gidx, c2_b1, c2_w2, c2_b2, gx2);
    cudaEventRecord(c.eX2, s0);

    cudaStreamWaitEvent(s1, c.eX2, 0);
    ab_kernel<8><<<NB / 8, 256, 0, s1>>>(gx2, c3_w1, 128, 256, gA, gB);
    cudaEventRecord(c.eA3, s1);

    d2_kernel<<<dg, 256, 0, s0>>>(gx2, 128, gd2);
    topk_kernel<<<NB / 4, 256, 0, s0>>>(gd2, gidx);

    cudaStreamWaitEvent(s0, c.eA3, 0);
    edge3_kernel<<<NB / E3_NPB, 256, 0, s0>>>(gA, gB, gidx, c3_b1, gw2p, c3_b2, gx3);

    sf_kernel<<<NB / SF_NPB, 256, 0, s0>>>(gx1, gx2, gx3, gsmw1p, sm_b1, gsmw2p, sm_b2, gecw1p,
                                           gsf, ghi, ghj);

    gmax_kernel<<<BATCH, 1024, 0, s0>>>(gsf, ec_w1, ec_b1, ghg);

    int writeBoth = (out_size >= 2 * BATCH * NPAIR) ? 1 : 0;
    dim3 grid(16, 16, BATCH);
    pairs_kernel<<<grid, 256, 0, s0>>>(ghi, ghj, ghg, ec_w2, ec_b2, (float*)d_out, writeBoth);
}

// round 15
// speedup vs baseline: 1.0517x; 1.0517x over previous
#include <cuda_runtime.h>
#include <math.h>

#define BATCH 2
#define NPT   1000
#define KNN   8
#define NPAIR 499500   // N*(N-1)/2

typedef unsigned long long u64;
typedef unsigned int u32;

// ---------------- static scratch (no allocation allowed) ----------------
__device__ float g_x1[BATCH * NPT * 32];
__device__ float g_x2[BATCH * NPT * 128];
__device__ float g_x3[BATCH * NPT * 512];
__device__ int   g_idx[BATCH * NPT * KNN];
__device__ float g_A [BATCH * NPT * 256];
__device__ float g_Bv[BATCH * NPT * 256];
__device__ float g_sf[BATCH * NPT * 128];
__device__ float g_hi[BATCH * NPT * 128];
__device__ float g_hj[BATCH * NPT * 128];
__device__ float g_hg[BATCH * 128];
__device__ float g_d2[(size_t)BATCH * NPT * NPT];
__device__ u32 g_w2t  [256 * 512];   // conv3 w2 as TF32 (rna-rounded), [h][col]
__device__ u64 g_smw1p[336 * 256];   // sm_w1 packed f32x2 over d
__device__ u64 g_smw2p[128 * 128];   // sm_w2 packed over d
__device__ u64 g_ecw1p[128 * 128];   // ec_w1[:256] packed over d (two 64x128 halves)

// ---------------- f32x2 packed helpers ----------------
__device__ __forceinline__ u64 ffma2(u64 a, u64 b, u64 c) {
    u64 d;
    asm("fma.rn.f32x2 %0, %1, %2, %3;" : "=l"(d) : "l"(a), "l"(b), "l"(c));
    return d;
}
__device__ __forceinline__ void unpack2(u64 v, float& lo, float& hi) {
    asm("mov.b64 {%0, %1}, %2;" : "=f"(lo), "=f"(hi) : "l"(v));
}
__device__ __forceinline__ u64 pack2(float lo, float hi) {
    u64 v;
    asm("mov.b64 %0, {%1, %2};" : "=l"(v) : "f"(lo), "f"(hi));
    return v;
}
__device__ __forceinline__ u32 to_tf32(float f) {
    u32 r;
    asm("cvt.rna.tf32.f32 %0, %1;" : "=r"(r) : "f"(f));
    return r;
}

// ---------------- combined weight packing ----------------
#define PK_W2T  (256 * 512)
#define PK_SMW1 (336 * 256)
#define PK_SMW2 (128 * 128)
#define PK_EC   (128 * 128)
#define PK_TOTAL (PK_W2T + PK_SMW1 + PK_SMW2 + PK_EC)
__global__ void pack_all_kernel(const float* __restrict__ c3w2, const float* __restrict__ smw1,
                                const float* __restrict__ smw2, const float* __restrict__ ecw1,
                                u32* __restrict__ w2t, u64* __restrict__ smw1p,
                                u64* __restrict__ smw2p, u64* __restrict__ ecw1p) {
    int idx = blockIdx.x * blockDim.x + threadIdx.x;
    if (idx < PK_W2T) {
        w2t[idx] = to_tf32(c3w2[idx]);
        return;
    }
    idx -= PK_W2T;
    if (idx < PK_SMW1) {
        int d2 = idx >> 8, col = idx & 255;
        smw1p[idx] = pack2(smw1[(2 * d2) * 256 + col], smw1[(2 * d2 + 1) * 256 + col]);
        return;
    }
    idx -= PK_SMW1;
    if (idx < PK_SMW2) {
        int d2 = idx >> 7, col = idx & 127;
        smw2p[idx] = pack2(smw2[(2 * d2) * 128 + col], smw2[(2 * d2 + 1) * 128 + col]);
        return;
    }
    idx -= PK_SMW2;
    {
        int half = idx >= 64 * 128;
        int i = idx - half * 64 * 128;
        int d2 = i >> 7, col = i & 127;
        int r0 = half * 128 + 2 * d2;
        ecw1p[idx] = pack2(ecw1[r0 * 128 + col], ecw1[(r0 + 1) * 128 + col]);
    }
}

// ---------------- pairwise ranking value: s[i][j] = |xj|^2 - 2*dot(xi,xj) ----------------
__global__ void d2_kernel(const float* __restrict__ x, int C, float* __restrict__ out) {
    int b  = blockIdx.z;
    int i0 = blockIdx.y * 64;
    int j0 = blockIdx.x * 64;
    __shared__ float xaT[16][72];
    __shared__ float xbT[16][72];

    int tid = threadIdx.x;          // 256
    int tx = tid & 15, ty = tid >> 4;

    float dot[4][4];
    float sqj[4];
#pragma unroll
    for (int v = 0; v < 4; v++) sqj[v] = 0.f;
#pragma unroll
    for (int u = 0; u < 4; u++)
#pragma unroll
        for (int v = 0; v < 4; v++) dot[u][v] = 0.f;

    for (int k0 = 0; k0 < C; k0 += 16) {
        for (int t = tid; t < 2048; t += 256) {
            int half = t >> 10;
            int r  = (t >> 4) & 63;
            int kk = t & 15;
            int cc = k0 + kk;
            int nn = (half ? j0 : i0) + r;
            float v = 0.f;
            if (cc < C && nn < NPT) v = x[((size_t)(b * NPT + nn)) * C + cc];
            if (half) xbT[kk][r] = v; else xaT[kk][r] = v;
        }
        __syncthreads();
#pragma unroll
        for (int kk = 0; kk < 16; kk++) {
            float4 a  = *reinterpret_cast<const float4*>(&xaT[kk][ty * 4]);
            float4 bb = *reinterpret_cast<const float4*>(&xbT[kk][tx * 4]);
            float av[4] = {a.x, a.y, a.z, a.w};
            float bv[4] = {bb.x, bb.y, bb.z, bb.w};
#pragma unroll
            for (int v = 0; v < 4; v++) sqj[v] = fmaf(bv[v], bv[v], sqj[v]);
#pragma unroll
            for (int u = 0; u < 4; u++)
#pragma unroll
                for (int v = 0; v < 4; v++)
                    dot[u][v] = fmaf(av[u], bv[v], dot[u][v]);
        }
        __syncthreads();
    }
#pragma unroll
    for (int u = 0; u < 4; u++) {
        int i = i0 + ty * 4 + u;
        if (i >= NPT) continue;
#pragma unroll
        for (int v = 0; v < 4; v++) {
            int j = j0 + tx * 4 + v;
            if (j >= NPT) continue;
            out[(size_t)(b * NPT + i) * NPT + j] = sqj[v] - 2.f * dot[u][v];
        }
    }
}

// ---------------- top-8 per row: TWO warps per row, branchless insert ----------------
__global__ void topk_kernel(const float* __restrict__ d2, int* __restrict__ idxout) {
    int warp = threadIdx.x >> 5, lane = threadIdx.x & 31;
    int r = warp >> 1;
    int h = warp & 1;
    int node = blockIdx.x * 4 + r;
    const float* row = d2 + (size_t)node * NPT;
    int L = h * 32 + lane;

    float bd[8]; int bi[8];
#pragma unroll
    for (int s = 0; s < 8; s++) { bd[s] = 3.4e38f; bi[s] = 0x7fffffff; }

#pragma unroll
    for (int cc = 0; cc < 2; cc++) {
        float v[8]; int jj[8];
#pragma unroll
        for (int q = 0; q < 8; q++) {
            int j = ((cc * 8 + q) * 2 + h) * 32 + lane;
            jj[q] = j;
            v[q] = (j < NPT) ? row[j] : 3.4e38f;
        }
#pragma unroll
        for (int q = 0; q < 8; q++) {
            float vv = v[q]; int vj = jj[q];
#pragma unroll
            for (int s = 0; s < 8; s++) {
                bool take = vv < bd[s];
                float tb = bd[s]; int ti = bi[s];
                bd[s] = take ? vv : tb;
                bi[s] = take ? vj : ti;
                vv = take ? tb : vv;
                vj = take ? ti : vj;
            }
        }
    }

    __shared__ float sd[4][64][8];
    __shared__ int   si[4][64][8];
#pragma unroll
    for (int s = 0; s < 8; s++) { sd[r][L][s] = bd[s]; si[r][L][s] = bi[s]; }
    __syncthreads();

    for (int str = 32; str > 0; str >>= 1) {
        if (L < str) {
            float* A1 = sd[r][L];        int* I1 = si[r][L];
            float* A2 = sd[r][L + str];  int* I2 = si[r][L + str];
            float od[8]; int oi[8];
            int a = 0, c2 = 0;
#pragma unroll
            for (int t = 0; t < 8; t++) {
                bool takeA = (A1[a] < A2[c2]) || (A1[a] == A2[c2] && I1[a] <= I2[c2]);
                if (takeA) { od[t] = A1[a]; oi[t] = I1[a]; a++; }
                else       { od[t] = A2[c2]; oi[t] = I2[c2]; c2++; }
            }
#pragma unroll
            for (int t = 0; t < 8; t++) { A1[t] = od[t]; I1[t] = oi[t]; }
        }
        __syncthreads();
    }
    if (L < 8) idxout[(size_t)node * 8 + L] = si[r][0][L];
}

// ---------------- small ab: one thread per (node, h) output ----------------
__global__ void ab_small_kernel(const float* __restrict__ x, const float* __restrict__ w1,
                                int C, int H, float* __restrict__ A, float* __restrict__ Bv) {
    int gid = blockIdx.x * blockDim.x + threadIdx.x;
    if (gid >= BATCH * NPT * H) return;
    int node = gid / H, h = gid % H;
    const float* xr = x + (size_t)node * C;
    float a = 0.f, bb = 0.f;
    for (int c = 0; c < C; c++) {
        float v = xr[c];
        a  = fmaf(v, w1[c * H + h],       a);
        bb = fmaf(v, w1[(C + c) * H + h], bb);
    }
    A[gid] = a; Bv[gid] = bb;
}

// ---------------- big ab (conv3): 8 nodes/block, 256 threads ----------------
template<int NPB>
__global__ void ab_kernel(const float* __restrict__ x, const float* __restrict__ w1,
                          int C, int H, float* __restrict__ A, float* __restrict__ Bv) {
    int n0 = blockIdx.x * NPB;
    int tid = threadIdx.x;          // H threads
    __shared__ float xs[NPB][128];
    for (int t = tid; t < NPB * C; t += blockDim.x) {
        int nn = t / C, c = t % C;
        xs[nn][c] = x[(size_t)(n0 + nn) * C + c];
    }
    __syncthreads();
    float a[NPB], bb[NPB];
#pragma unroll
    for (int nn = 0; nn < NPB; nn++) { a[nn] = 0.f; bb[nn] = 0.f; }
    for (int c = 0; c < C; c++) {
        float wt = w1[c * H + tid];
        float wb = w1[(C + c) * H + tid];
#pragma unroll
        for (int nn = 0; nn < NPB; nn++) {
            float v = xs[nn][c];
            a[nn]  = fmaf(v, wt, a[nn]);
            bb[nn] = fmaf(v, wb, bb[nn]);
        }
    }
#pragma unroll
    for (int nn = 0; nn < NPB; nn++) {
        A [(size_t)(n0 + nn) * H + tid] = a[nn];
        Bv[(size_t)(n0 + nn) * H + tid] = bb[nn];
    }
}

// ---------------- conv1 edge: warp-per-node, 256 threads = 8 nodes/block ----------------
__global__ void edge1_kernel(const float* __restrict__ A, const float* __restrict__ Bv,
                             const int* __restrict__ idx, const float* __restrict__ b1,
                             const float* __restrict__ w2, const float* __restrict__ b2,
                             float* __restrict__ xout) {
    const int H = 16, COUT = 32;
    int warp = threadIdx.x >> 5, lane = threadIdx.x & 31;
    int node = blockIdx.x * 8 + warp;
    int bbase = (node / NPT) * NPT;

    __shared__ float aic[8][H];
    __shared__ float hsh[8][KNN][H];
    __shared__ int   js[8][KNN];

    if (lane < KNN) js[warp][lane] = idx[(size_t)node * KNN + lane];
    if (lane < H)
        aic[warp][lane] = A[(size_t)node * H + lane] - Bv[(size_t)node * H + lane] + b1[lane];
    __syncwarp();

#pragma unroll
    for (int q = 0; q < 4; q++) {
        int t = lane + q * 32;
        int k = t >> 4, hh = t & 15;
        hsh[warp][k][hh] = fmaxf(aic[warp][hh] + Bv[(size_t)(bbase + js[warp][k]) * H + hh], 0.f);
    }
    __syncwarp();

    float acc[KNN];
#pragma unroll
    for (int k = 0; k < KNN; k++) acc[k] = 0.f;
#pragma unroll
    for (int hh = 0; hh < H; hh++) {
        float w = w2[hh * COUT + lane];
#pragma unroll
        for (int k = 0; k < KNN; k++) acc[k] = fmaf(hsh[warp][k][hh], w, acc[k]);
    }
    float m = acc[0];
#pragma unroll
    for (int k = 1; k < KNN; k++) m = fmaxf(m, acc[k]);
    xout[(size_t)node * COUT + lane] = m + b2[lane];
}

// ---------------- edge MLP2 + max, generic (conv2) ----------------
template<int H, int COUT, int T, int VC, int NPB>
__global__ void edge_kernel(const float* __restrict__ A, const float* __restrict__ Bv,
                            const int* __restrict__ idx, const float* __restrict__ b1,
                            const float* __restrict__ w2, const float* __restrict__ b2,
                            float* __restrict__ xout) {
    static_assert(T * VC == COUT, "layout");
    int n0 = blockIdx.x * NPB;
    int tid = threadIdx.x;
    __shared__ float aic[NPB][H];
    __shared__ float hsh[NPB][KNN][H];
    __shared__ int   js[NPB][KNN];

    for (int t = tid; t < NPB * KNN; t += T)
        js[t / KNN][t % KNN] = idx[(size_t)(n0 + t / KNN) * KNN + t % KNN];
#pragma unroll
    for (int n = 0; n < NPB; n++)
        for (int hh = tid; hh < H; hh += T)
            aic[n][hh] = A[(size_t)(n0 + n) * H + hh] - Bv[(size_t)(n0 + n) * H + hh] + b1[hh];
    __syncthreads();

    int bbase = (n0 / NPT) * NPT;
#pragma unroll
    for (int n = 0; n < NPB; n++)
#pragma unroll
        for (int k = 0; k < KNN; k++) {
            const float* bvj = Bv + (size_t)(bbase + js[n][k]) * H;
            for (int hh = tid; hh < H; hh += T)
                hsh[n][k][hh] = fmaxf(aic[n][hh] + bvj[hh], 0.f);
        }
    __syncthreads();

    float acc[NPB][KNN][VC];
#pragma unroll
    for (int n = 0; n < NPB; n++)
#pragma unroll
        for (int k = 0; k < KNN; k++)
#pragma unroll
            for (int v = 0; v < VC; v++) acc[n][k][v] = 0.f;

#pragma unroll 2
    for (int hh = 0; hh < H; hh++) {
        float w[VC];
#pragma unroll
        for (int v = 0; v < VC; v++) w[v] = w2[(size_t)hh * COUT + tid * VC + v];
#pragma unroll
        for (int n = 0; n < NPB; n++)
#pragma unroll
            for (int k = 0; k < KNN; k++) {
                float hv = hsh[n][k][hh];
#pragma unroll
                for (int v = 0; v < VC; v++) acc[n][k][v] = fmaf(hv, w[v], acc[n][k][v]);
            }
    }

#pragma unroll
    for (int n = 0; n < NPB; n++)
#pragma unroll
        for (int v = 0; v < VC; v++) {
            float m = -3.4e38f;
#pragma unroll
            for (int k = 0; k < KNN; k++) m = fmaxf(m, acc[n][k][v]);
            xout[(size_t)(n0 + n) * COUT + tid * VC + v] = m + b2[tid * VC + v];
        }
}

// ---------------- edge conv3: TF32 tensor-core mma.sync ----------------
// Block: 8 nodes (M=64 edges), N-half of 256 cols (grid.y=2). 256 threads.
// smem (dynamic): hshT u32[64][260], aic f32[8][256], bs u32[8][264], js int[64]
#define E3_HSTRIDE 260
#define E3_BSTRIDE 264
#define E3_SMEM_U32 (64 * E3_HSTRIDE + 8 * 256 + 8 * E3_BSTRIDE + 64)
__global__ void edge3_tc_kernel(const float* __restrict__ A, const float* __restrict__ Bv,
                                const int* __restrict__ idx, const float* __restrict__ b1,
                                const u32* __restrict__ w2t, const float* __restrict__ b2,
                                float* __restrict__ xout) {
    extern __shared__ u32 sdyn[];
    u32*   hshT = sdyn;                                  // [64][260]
    float* aic  = (float*)(sdyn + 64 * E3_HSTRIDE);      // [8][256]
    u32*   bs   = sdyn + 64 * E3_HSTRIDE + 8 * 256;      // [8][264]
    int*   js   = (int*)(sdyn + 64 * E3_HSTRIDE + 8 * 256 + 8 * E3_BSTRIDE); // [64]

    int tid = threadIdx.x;
    int n0 = blockIdx.x * 8;
    int cb = blockIdx.y * 256;          // column half base
    int bbase = (n0 / NPT) * NPT;

    for (int t = tid; t < 64; t += 256)
        js[t] = idx[(size_t)(n0 + (t >> 3)) * KNN + (t & 7)];
    for (int t = tid; t < 8 * 256; t += 256) {
        int nn = t >> 8, kk = t & 255;
        aic[t] = A[(size_t)(n0 + nn) * 256 + kk] - Bv[(size_t)(n0 + nn) * 256 + kk] + b1[kk];
    }
    __syncthreads();

    // build hsh (tf32-rounded): 64 edges x 256
    for (int t = tid; t < 64 * 256; t += 256) {
        int e = t >> 8, kk = t & 255;
        float v = fmaxf(aic[(e >> 3) * 256 + kk] + Bv[(size_t)(bbase + js[e]) * 256 + kk], 0.f);
        hshT[e * E3_HSTRIDE + kk] = to_tf32(v);
    }

    int warp = tid >> 5, lane = tid & 31;
    int mt = warp & 3;                  // m-tile: edges mt*16 .. mt*16+15
    int nb = (warp >> 2) * 128;         // n offset within this 256-half

    float acc[16][4];
#pragma unroll
    for (int nt = 0; nt < 16; nt++)
#pragma unroll
        for (int v = 0; v < 4; v++) acc[nt][v] = 0.f;

    int g = lane >> 2, kk4 = lane & 3;
    int r0 = mt * 16 + g;
    const u32* a0p = &hshT[r0 * E3_HSTRIDE + kk4];
    const u32* a1p = &hshT[(r0 + 8) * E3_HSTRIDE + kk4];
    const u32* b0base = &bs[kk4 * E3_BSTRIDE + nb + g];
    const u32* b1base = &bs[(kk4 + 4) * E3_BSTRIDE + nb + g];

    for (int k0 = 0; k0 < 256; k0 += 8) {
        __syncthreads();   // prior mma reads of bs done (also covers hsh build on first iter)
        for (int t = tid; t < 2048; t += 256) {
            int kk = t >> 8, n = t & 255;
            bs[kk * E3_BSTRIDE + n] = w2t[(size_t)(k0 + kk) * 512 + cb + n];
        }
        __syncthreads();

        u32 a0 = a0p[k0], a1 = a1p[k0], a2 = a0p[k0 + 4], a3 = a1p[k0 + 4];
#pragma unroll
        for (int nt = 0; nt < 16; nt++) {
            u32 bb0 = b0base[nt * 8];
            u32 bb1 = b1base[nt * 8];
            asm volatile(
                "mma.sync.aligned.m16n8k8.row.col.f32.tf32.tf32.f32 "
                "{%0,%1,%2,%3}, {%4,%5,%6,%7}, {%8,%9}, {%0,%1,%2,%3};"
                : "+f"(acc[nt][0]), "+f"(acc[nt][1]), "+f"(acc[nt][2]), "+f"(acc[nt][3])
                : "r"(a0), "r"(a1), "r"(a2), "r"(a3), "r"(bb0), "r"(bb1));
        }
    }

    // epilogue: max over the 8 edges of each node (rows 0-7 -> node0, 8-15 -> node1)
    int node0 = n0 + mt * 2;
#pragma unroll
    for (int nt = 0; nt < 16; nt++) {
        float c0 = acc[nt][0], c1 = acc[nt][1], c2 = acc[nt][2], c3 = acc[nt][3];
#pragma unroll
        for (int s = 4; s <= 16; s <<= 1) {
            c0 = fmaxf(c0, __shfl_xor_sync(0xffffffffu, c0, s));
            c1 = fmaxf(c1, __shfl_xor_sync(0xffffffffu, c1, s));
            c2 = fmaxf(c2, __shfl_xor_sync(0xffffffffu, c2, s));
            c3 = fmaxf(c3, __shfl_xor_sync(0xffffffffu, c3, s));
        }
        if (lane < 4) {
            int col = cb + nb + nt * 8 + lane * 2;
            xout[(size_t)node0 * 512 + col]       = c0 + b2[col];
            xout[(size_t)node0 * 512 + col + 1]   = c1 + b2[col + 1];
            xout[(size_t)(node0 + 1) * 512 + col]     = c2 + b2[col];
            xout[(size_t)(node0 + 1) * 512 + col + 1] = c3 + b2[col + 1];
        }
    }
}

// ---------------- sf = MLP(concat(x1,x2,x3)) + hi/hj projections, f32x2 ----------------
#define SF_NPB 8
__global__ void sf_kernel(const float* __restrict__ x1, const float* __restrict__ x2,
                          const float* __restrict__ x3,
                          const u64* __restrict__ w1p, const float* __restrict__ b1,
                          const u64* __restrict__ w2p, const float* __restrict__ b2,
                          const u64* __restrict__ ecw1p,
                          float* __restrict__ sf, float* __restrict__ hi, float* __restrict__ hj) {
    int n0 = blockIdx.x * SF_NPB;
    int tid = threadIdx.x;   // 256
    __shared__ __align__(16) float xin[SF_NPB][672];
    __shared__ __align__(16) float hsh[SF_NPB][256];
    __shared__ __align__(16) float sfs[SF_NPB][128];

    for (int t = tid; t < SF_NPB * 32; t += 256)
        xin[t >> 5][t & 31] = x1[(size_t)(n0 + (t >> 5)) * 32 + (t & 31)];
    for (int t = tid; t < SF_NPB * 128; t += 256)
        xin[t >> 7][32 + (t & 127)] = x2[(size_t)(n0 + (t >> 7)) * 128 + (t & 127)];
    for (int t = tid; t < SF_NPB * 512; t += 256)
        xin[t >> 9][160 + (t & 511)] = x3[(size_t)(n0 + (t >> 9)) * 512 + (t & 511)];
    __syncthreads();

    {
        u64 acc2[SF_NPB];
#pragma unroll
        for (int n = 0; n < SF_NPB; n++) acc2[n] = 0ull;
#pragma unroll 2
        for (int d2 = 0; d2 < 336; d2++) {
            u64 wv = w1p[d2 * 256 + tid];
#pragma unroll
            for (int n = 0; n < SF_NPB; n++) {
                u64 xv = reinterpret_cast<const u64*>(xin[n])[d2];
                acc2[n] = ffma2(xv, wv, acc2[n]);
            }
        }
        float bv = b1[tid];
#pragma unroll
        for (int n = 0; n < SF_NPB; n++) {
            float lo, hi2;
            unpack2(acc2[n], lo, hi2);
            hsh[n][tid] = fmaxf(lo + hi2 + bv, 0.f);
        }
    }
    __syncthreads();

    int col = tid & 127;
    int gn = (tid >> 7) * (SF_NPB / 2);
    {
        u64 acc2[SF_NPB / 2];
#pragma unroll
        for (int n = 0; n < SF_NPB / 2; n++) acc2[n] = 0ull;
#pragma unroll 4
        for (int d2 = 0; d2 < 128; d2++) {
            u64 wv = w2p[d2 * 128 + col];
#pragma unroll
            for (int n = 0; n < SF_NPB / 2; n++) {
                u64 hv = reinterpret_cast<const u64*>(hsh[gn + n])[d2];
                acc2[n] = ffma2(hv, wv, acc2[n]);
            }
        }
        float bv = b2[col];
#pragma unroll
        for (int n = 0; n < SF_NPB / 2; n++) {
            float lo, hi2;
            unpack2(acc2[n], lo, hi2);
            float v = lo + hi2 + bv;
            sfs[gn + n][col] = v;
            sf[(size_t)(n0 + gn + n) * 128 + col] = v;
        }
    }
    __syncthreads();

    {
        u64 a1[SF_NPB / 2], a2[SF_NPB / 2];
#pragma unroll
        for (int n = 0; n < SF_NPB / 2; n++) { a1[n] = 0ull; a2[n] = 0ull; }
#pragma unroll 4
        for (int d2 = 0; d2 < 64; d2++) {
            u64 wt = ecw1p[d2 * 128 + col];
            u64 wb = ecw1p[(64 + d2) * 128 + col];
#pragma unroll
            for (int n = 0; n < SF_NPB / 2; n++) {
                u64 s = reinterpret_cast<const u64*>(sfs[gn + n])[d2];
                a1[n] = ffma2(s, wt, a1[n]);
                a2[n] = ffma2(s, wb, a2[n]);
            }
        }
#pragma unroll
        for (int n = 0; n < SF_NPB / 2; n++) {
            float lo, hi2;
            unpack2(a1[n], lo, hi2);
            hi[(size_t)(n0 + gn + n) * 128 + col] = lo + hi2;
            unpack2(a2[n], lo, hi2);
            hj[(size_t)(n0 + gn + n) * 128 + col] = lo + hi2;
        }
    }
}

// ---------------- global max pool + hg, parallel ----------------
__global__ void gmax_kernel(const float* __restrict__ sf, const float* __restrict__ ecw1,
                            const float* __restrict__ ecb1, float* __restrict__ hg) {
    int b = blockIdx.x;
    int tid = threadIdx.x;  // 1024
    int col = tid & 127, seg = tid >> 7;
    __shared__ float part[8][128];
    __shared__ float gsh[128];
    float m = -3.4e38f;
    for (int n = seg; n < NPT; n += 8)
        m = fmaxf(m, sf[(size_t)(b * NPT + n) * 128 + col]);
    part[seg][col] = m;
    __syncthreads();
    if (tid < 128) {
        float mm = part[0][tid];
#pragma unroll
        for (int s = 1; s < 8; s++) mm = fmaxf(mm, part[s][tid]);
        gsh[tid] = mm;
    }
    __syncthreads();
    if (tid < 128) {
        float acc = ecb1[tid];
#pragma unroll 8
        for (int d = 0; d < 128; d++)
            acc = fmaf(gsh[d], ecw1[(256 + d) * 128 + tid], acc);
        hg[b * 128 + tid] = acc;
    }
}

// ---------------- all-pairs: 64x64 pair tiles, 4x4 register block ----------------
__global__ void pairs_kernel(const float* __restrict__ hi, const float* __restrict__ hj,
                             const float* __restrict__ hg, const float* __restrict__ ecw2,
                             const float* __restrict__ ecb2, float* __restrict__ out,
                             int writeBoth) {
    int it = blockIdx.x, jt = blockIdx.y, b = blockIdx.z;
    if (jt < it) return;

    __shared__ float his[16][68];
    __shared__ float hjs[16][68];
    __shared__ float w2s[128];

    int tid = threadIdx.x;  // 256
    if (tid < 128) w2s[tid] = ecw2[tid];
    int tx = tid & 15, ty = tid >> 4;

    float acc[4][4];
#pragma unroll
    for (int u = 0; u < 4; u++)
#pragma unroll
        for (int v = 0; v < 4; v++) acc[u][v] = 0.f;

    for (int c0 = 0; c0 < 128; c0 += 16) {
        __syncthreads();
        for (int t = tid; t < 1024; t += 256) {
            int r = t >> 4, c = t & 15;
            int gi = it * 64 + r;
            his[c][r] = (gi < NPT)
                ? hi[(size_t)(b * NPT + gi) * 128 + c0 + c] + hg[b * 128 + c0 + c] : 0.f;
            int gj = jt * 64 + r;
            hjs[c][r] = (gj < NPT) ? hj[(size_t)(b * NPT + gj) * 128 + c0 + c] : 0.f;
        }
        __syncthreads();
#pragma unroll
        for (int c = 0; c < 16; c++) {
            float w = w2s[c0 + c];
            float4 a  = *reinterpret_cast<const float4*>(&his[c][ty * 4]);
            float4 bb = *reinterpret_cast<const float4*>(&hjs[c][tx * 4]);
            float av[4] = {a.x, a.y, a.z, a.w};
            float bv[4] = {bb.x, bb.y, bb.z, bb.w};
#pragma unroll
            for (int u = 0; u < 4; u++)
#pragma unroll
                for (int v = 0; v < 4; v++)
                    acc[u][v] = fmaf(fmaxf(av[u] + bv[v], 0.f), w, acc[u][v]);
        }
    }

    float bias = ecb2[0];
#pragma unroll
    for (int u = 0; u < 4; u++) {
        int i = it * 64 + ty * 4 + u;
        if (i >= NPT) continue;
        size_t rowbase = (size_t)b * NPAIR
                       + (size_t)i * (NPT - 1) - (size_t)i * (i - 1) / 2 - i - 1;
#pragma unroll
        for (int v = 0; v < 4; v++) {
            int j = jt * 64 + tx * 4 + v;
            if (j >= NPT || j <= i) continue;
            float val = acc[u][v] + bias;
            float prob = 1.f / (1.f + __expf(-val));
            size_t o = rowbase + j;
            out[o] = prob;
            if (writeBoth) out[(size_t)BATCH * NPAIR + o] = val;
        }
    }
}

// ---------------- stream/event context (created once, host-side only) ----------------
struct OverlapCtx {
    cudaStream_t s1;
    cudaEvent_t e0, eA1, eX1, eA2, eX2, eA3;
    OverlapCtx() {
        cudaStreamCreateWithFlags(&s1, cudaStreamNonBlocking);
        unsigned f = cudaEventDisableTiming;
        cudaEventCreateWithFlags(&e0, f);
        cudaEventCreateWithFlags(&eA1, f);
        cudaEventCreateWithFlags(&eX1, f);
        cudaEventCreateWithFlags(&eA2, f);
        cudaEventCreateWithFlags(&eX2, f);
        cudaEventCreateWithFlags(&eA3, f);
        cudaFuncSetAttribute(edge3_tc_kernel,
                             cudaFuncAttributeMaxDynamicSharedMemorySize,
                             E3_SMEM_U32 * 4);
    }
};
static OverlapCtx& octx() { static OverlapCtx c; return c; }

// ---------------- host launch ----------------
extern "C" void kernel_launch(void* const* d_in, const int* in_sizes, int n_in,
                              void* d_out, int out_size) {
    const float* pos   = (const float*)d_in[0];
    const float* c1_w1 = (const float*)d_in[1];
    const float* c1_b1 = (const float*)d_in[2];
    const float* c1_w2 = (const float*)d_in[3];
    const float* c1_b2 = (const float*)d_in[4];
    const float* c2_w1 = (const float*)d_in[5];
    const float* c2_b1 = (const float*)d_in[6];
    const float* c2_w2 = (const float*)d_in[7];
    const float* c2_b2 = (const float*)d_in[8];
    const float* c3_w1 = (const float*)d_in[9];
    const float* c3_b1 = (const float*)d_in[10];
    const float* c3_w2 = (const float*)d_in[11];
    const float* c3_b2 = (const float*)d_in[12];
    const float* sm_w1 = (const float*)d_in[13];
    const float* sm_b1 = (const float*)d_in[14];
    const float* sm_w2 = (const float*)d_in[15];
    const float* sm_b2 = (const float*)d_in[16];
    const float* ec_w1 = (const float*)d_in[17];
    const float* ec_b1 = (const float*)d_in[18];
    const float* ec_w2 = (const float*)d_in[19];
    const float* ec_b2 = (const float*)d_in[20];

    float *gx1, *gx2, *gx3, *gA, *gB, *gsf, *ghi, *ghj, *ghg, *gd2;
    u32* gw2t;
    u64 *gsmw1p, *gsmw2p, *gecw1p;
    int* gidx;
    cudaGetSymbolAddress((void**)&gx1, g_x1);
    cudaGetSymbolAddress((void**)&gx2, g_x2);
    cudaGetSymbolAddress((void**)&gx3, g_x3);
    cudaGetSymbolAddress((void**)&gidx, g_idx);
    cudaGetSymbolAddress((void**)&gA,  g_A);
    cudaGetSymbolAddress((void**)&gB,  g_Bv);
    cudaGetSymbolAddress((void**)&gsf, g_sf);
    cudaGetSymbolAddress((void**)&ghi, g_hi);
    cudaGetSymbolAddress((void**)&ghj, g_hj);
    cudaGetSymbolAddress((void**)&ghg, g_hg);
    cudaGetSymbolAddress((void**)&gd2, g_d2);
    cudaGetSymbolAddress((void**)&gw2t, g_w2t);
    cudaGetSymbolAddress((void**)&gsmw1p, g_smw1p);
    cudaGetSymbolAddress((void**)&gsmw2p, g_smw2p);
    cudaGetSymbolAddress((void**)&gecw1p, g_ecw1p);

    const int NB = BATCH * NPT;
    OverlapCtx& c = octx();
    cudaStream_t s0 = 0;
    cudaStream_t s1 = c.s1;
    dim3 dg(16, 16, BATCH);

    cudaEventRecord(c.e0, s0);
    cudaStreamWaitEvent(s1, c.e0, 0);

    pack_all_kernel<<<(PK_TOTAL + 255) / 256, 256, 0, s1>>>(c3_w2, sm_w1, sm_w2, ec_w1,
                                                            gw2t, gsmw1p, gsmw2p, gecw1p);
    ab_small_kernel<<<(NB * 16 + 255) / 256, 256, 0, s1>>>(pos, c1_w1, 3, 16, gA, gB);
    cudaEventRecord(c.eA1, s1);

    d2_kernel<<<dg, 256, 0, s0>>>(pos, 3, gd2);
    topk_kernel<<<NB / 4, 256, 0, s0>>>(gd2, gidx);

    cudaStreamWaitEvent(s0, c.eA1, 0);
    edge1_kernel<<<NB / 8, 256, 0, s0>>>(gA, gB, gidx, c1_b1, c1_w2, c1_b2, gx1);
    cudaEventRecord(c.eX1, s0);

    cudaStreamWaitEvent(s1, c.eX1, 0);
    ab_small_kernel<<<(NB * 64 + 255) / 256, 256, 0, s1>>>(gx1, c2_w1, 32, 64, gA, gB);
    cudaEventRecord(c.eA2, s1);

    d2_kernel<<<dg, 256, 0, s0>>>(gx1, 32, gd2);
    topk_kernel<<<NB / 4, 256, 0, s0>>>(gd2, gidx);

    cudaStreamWaitEvent(s0, c.eA2, 0);
    edge_kernel<64, 128, 128, 1, 4><<<NB / 4, 128, 0, s0>>>(gA, gB, gidx, c2_b1, c2_w2, c2_b2, gx2);
    cudaEventRecord(c.eX2, s0);

    cudaStreamWaitEvent(s1, c.eX2, 0);
    ab_kernel<8><<<NB / 8, 256, 0, s1>>>(gx2, c3_w1, 128, 256, gA, gB);
    cudaEventRecord(c.eA3, s1);

    d2_kernel<<<dg, 256, 0, s0>>>(gx2, 128, gd2);
    topk_kernel<<<NB / 4, 256, 0, s0>>>(gd2, gidx);

    cudaStreamWaitEvent(s0, c.eA3, 0);
    {
        dim3 eg(NB / 8, 2);
        edge3_tc_kernel<<<eg, 256, E3_SMEM_U32 * 4, s0>>>(gA, gB, gidx, c3_b1, gw2t, c3_b2, gx3);
    }

    sf_kernel<<<NB / SF_NPB, 256, 0, s0>>>(gx1, gx2, gx3, gsmw1p, sm_b1, gsmw2p, sm_b2, gecw1p,
                                           gsf, ghi, ghj);

    gmax_kernel<<<BATCH, 1024, 0, s0>>>(gsf, ec_w1, ec_b1, ghg);

    int writeBoth = (out_size >= 2 * BATCH * NPAIR) ? 1 : 0;
    dim3 grid(16, 16, BATCH);
    pairs_kernel<<<grid, 256, 0, s0>>>(ghi, ghj, ghg, ec_w2, ec_b2, (float*)d_out, writeBoth);
}